// round 2
// baseline (speedup 1.0000x reference)
#include <cuda_runtime.h>

#define BATCH   8
#define NN      512
#define DD      64
#define KNODES  256
#define TILE    32
#define NTILES  16      // NN / TILE
#define NPAIRS  136     // NTILES*(NTILES+1)/2

// Scratch (device globals: no allocation allowed)
__device__ float g_logits[BATCH * NN * NN];   // 8 MB
__device__ float g_h[BATCH * NN * DD];        // 1 MB
__device__ float g_scores[BATCH * NN];

__device__ __forceinline__ float fast_tanh(float v) {
    float a = fabsf(v);
    float e = __expf(-2.0f * a);                 // MUFU.EX2 based
    float r = __fdividef(1.0f - e, 1.0f + e);    // MUFU.RCP based
    return copysignf(r, v);
}

// ---------------------------------------------------------------------------
// K1: pairwise logits. One CTA per (batch, upper-triangular 32x32 tile pair).
// logits[b,i,j] = sum_o tanh(b_o + sum_d x[b,i,d]*x[b,j,d]*W[d,o]) * attw[o]
// Symmetric in (i,j): compute upper triangle, mirror-store.
// ---------------------------------------------------------------------------
__global__ __launch_bounds__(256, 2)
void k1_logits(const float* __restrict__ x, const float* __restrict__ W,
               const float* __restrict__ pb, const float* __restrict__ attw) {
    __shared__ float xi_s[TILE][72];
    __shared__ float xj_s[TILE][72];
    __shared__ float wt[DD][72];      // wt[o][d] (transposed W)
    __shared__ float pb_s[DD], aw_s[DD];

    int b = blockIdx.y;
    int pp = blockIdx.x;
    int it = 0;
    while (pp >= NTILES - it) { pp -= NTILES - it; it++; }
    int jt = it + pp;

    int t = threadIdx.x;
    for (int idx = t; idx < DD * DD; idx += 256) {
        int d = idx >> 6, o = idx & 63;
        wt[o][d] = W[idx];            // W is [d][o] row-major
    }
    if (t < DD) { pb_s[t] = pb[t]; aw_s[t] = attw[t]; }
    const float* xb = x + (size_t)b * NN * DD;
    for (int idx = t; idx < TILE * 16; idx += 256) {
        int r = idx >> 4, c = idx & 15;
        float4 vi = ((const float4*)(xb + (it * TILE + r) * DD))[c];
        *(float4*)&xi_s[r][c * 4] = vi;
        float4 vj = ((const float4*)(xb + (jt * TILE + r) * DD))[c];
        *(float4*)&xj_s[r][c * 4] = vj;
    }
    __syncthreads();

    int tj = t & 15, ti = t >> 4;
    int i0 = 2 * ti, i1 = i0 + 1;     // warp: 4 distinct xi rows (broadcast within half-warp rows)
    int j0 = tj, j1 = tj + 16;        // warp: 16 rows stride-1; pad=72 keeps float4 phases distinct

    float lg00 = 0.f, lg01 = 0.f, lg10 = 0.f, lg11 = 0.f;

    #pragma unroll 1
    for (int oc = 0; oc < DD; oc += 8) {
        float acc[4][8];
        #pragma unroll
        for (int k = 0; k < 8; k++) {
            float bv = pb_s[oc + k];
            acc[0][k] = bv; acc[1][k] = bv; acc[2][k] = bv; acc[3][k] = bv;
        }
        #pragma unroll 4
        for (int d = 0; d < DD; d += 4) {
            float4 a0 = *(const float4*)&xi_s[i0][d];
            float4 a1 = *(const float4*)&xi_s[i1][d];
            float4 b0 = *(const float4*)&xj_s[j0][d];
            float4 b1 = *(const float4*)&xj_s[j1][d];
            float4 p00 = make_float4(a0.x*b0.x, a0.y*b0.y, a0.z*b0.z, a0.w*b0.w);
            float4 p01 = make_float4(a0.x*b1.x, a0.y*b1.y, a0.z*b1.z, a0.w*b1.w);
            float4 p10 = make_float4(a1.x*b0.x, a1.y*b0.y, a1.z*b0.z, a1.w*b0.w);
            float4 p11 = make_float4(a1.x*b1.x, a1.y*b1.y, a1.z*b1.z, a1.w*b1.w);
            #pragma unroll
            for (int k = 0; k < 8; k++) {
                float4 w = *(const float4*)&wt[oc + k][d];
                acc[0][k] = fmaf(p00.x, w.x, acc[0][k]);
                acc[0][k] = fmaf(p00.y, w.y, acc[0][k]);
                acc[0][k] = fmaf(p00.z, w.z, acc[0][k]);
                acc[0][k] = fmaf(p00.w, w.w, acc[0][k]);
                acc[1][k] = fmaf(p01.x, w.x, acc[1][k]);
                acc[1][k] = fmaf(p01.y, w.y, acc[1][k]);
                acc[1][k] = fmaf(p01.z, w.z, acc[1][k]);
                acc[1][k] = fmaf(p01.w, w.w, acc[1][k]);
                acc[2][k] = fmaf(p10.x, w.x, acc[2][k]);
                acc[2][k] = fmaf(p10.y, w.y, acc[2][k]);
                acc[2][k] = fmaf(p10.z, w.z, acc[2][k]);
                acc[2][k] = fmaf(p10.w, w.w, acc[2][k]);
                acc[3][k] = fmaf(p11.x, w.x, acc[3][k]);
                acc[3][k] = fmaf(p11.y, w.y, acc[3][k]);
                acc[3][k] = fmaf(p11.z, w.z, acc[3][k]);
                acc[3][k] = fmaf(p11.w, w.w, acc[3][k]);
            }
        }
        #pragma unroll
        for (int k = 0; k < 8; k++) {
            float aw = aw_s[oc + k];
            lg00 = fmaf(fast_tanh(acc[0][k]), aw, lg00);
            lg01 = fmaf(fast_tanh(acc[1][k]), aw, lg01);
            lg10 = fmaf(fast_tanh(acc[2][k]), aw, lg10);
            lg11 = fmaf(fast_tanh(acc[3][k]), aw, lg11);
        }
    }
    float* L = g_logits + (size_t)b * NN * NN;
    int gi0 = it * TILE + i0, gi1 = it * TILE + i1;
    int gj0 = jt * TILE + j0, gj1 = jt * TILE + j1;
    L[gi0 * NN + gj0] = lg00; L[gi0 * NN + gj1] = lg01;
    L[gi1 * NN + gj0] = lg10; L[gi1 * NN + gj1] = lg11;
    if (it != jt) {
        L[gj0 * NN + gi0] = lg00; L[gj1 * NN + gi0] = lg01;
        L[gj0 * NN + gi1] = lg10; L[gj1 * NN + gi1] = lg11;
    }
}

// ---------------------------------------------------------------------------
// K2: per (b, 8-row block): softmax over j, agg = att @ X, h = agg@pwa + x@pwo
//     + biases, BN(eval), SELU, score = sigmoid(h @ pool_w + pool_b)
// ---------------------------------------------------------------------------
__global__ __launch_bounds__(256)
void k2_softagg(const float* __restrict__ x,
                const float* __restrict__ pwa_w, const float* __restrict__ pwa_b,
                const float* __restrict__ pwo_w, const float* __restrict__ pwo_b,
                const float* __restrict__ bn_gamma, const float* __restrict__ bn_beta,
                const float* __restrict__ pool_w, const float* __restrict__ pool_b) {
    __shared__ float prob_s[NN][8];        // 16 KB: [j][r]
    __shared__ float part_s[4][8][DD];     // 8 KB
    __shared__ float agg_s[8][DD];
    __shared__ float xrow_s[8][DD];
    __shared__ float h_s[8][DD];
    __shared__ float inv_s[8];

    int b = blockIdx.y;
    int ibase = blockIdx.x * 8;
    int t = threadIdx.x;
    const float* xb = x + (size_t)b * NN * DD;

    for (int idx = t; idx < 8 * DD; idx += 256) {
        int r = idx >> 6, d = idx & 63;
        xrow_s[r][d] = xb[(ibase + r) * DD + d];
    }

    {   // softmax (unnormalized) for 8 rows: warp r handles row ibase+r
        int r = t >> 5, lane = t & 31;
        const float* Lrow = g_logits + ((size_t)b * NN + ibase + r) * NN;
        float lv[16];
        float m = -1e30f;
        #pragma unroll
        for (int q = 0; q < 16; q++) { lv[q] = Lrow[lane + q * 32]; m = fmaxf(m, lv[q]); }
        #pragma unroll
        for (int off = 16; off; off >>= 1) m = fmaxf(m, __shfl_xor_sync(0xffffffffu, m, off));
        float sum = 0.f;
        #pragma unroll
        for (int q = 0; q < 16; q++) {
            float e = __expf(lv[q] - m);
            prob_s[lane + q * 32][r] = e;
            sum += e;
        }
        #pragma unroll
        for (int off = 16; off; off >>= 1) sum += __shfl_xor_sync(0xffffffffu, sum, off);
        if (lane == 0) inv_s[r] = 1.0f / sum;
    }
    __syncthreads();

    {   // agg partials: thread = (d4 in 16, g in 4, rp in 4) -> 4 d x 2 rows
        int d4 = t & 15, g = (t >> 4) & 3, rp = t >> 6;
        int r0 = rp * 2;
        float a0x=0,a0y=0,a0z=0,a0w=0, a1x=0,a1y=0,a1z=0,a1w=0;
        const float4* xb4 = (const float4*)xb;
        for (int jj = 0; jj < 128; jj++) {
            int j = g * 128 + jj;
            float4 xv = xb4[j * 16 + d4];
            float2 pr = *(const float2*)&prob_s[j][r0];
            a0x = fmaf(pr.x, xv.x, a0x); a0y = fmaf(pr.x, xv.y, a0y);
            a0z = fmaf(pr.x, xv.z, a0z); a0w = fmaf(pr.x, xv.w, a0w);
            a1x = fmaf(pr.y, xv.x, a1x); a1y = fmaf(pr.y, xv.y, a1y);
            a1z = fmaf(pr.y, xv.z, a1z); a1w = fmaf(pr.y, xv.w, a1w);
        }
        part_s[g][r0][d4*4+0] = a0x; part_s[g][r0][d4*4+1] = a0y;
        part_s[g][r0][d4*4+2] = a0z; part_s[g][r0][d4*4+3] = a0w;
        part_s[g][r0+1][d4*4+0] = a1x; part_s[g][r0+1][d4*4+1] = a1y;
        part_s[g][r0+1][d4*4+2] = a1z; part_s[g][r0+1][d4*4+3] = a1w;
    }
    __syncthreads();

    if (t < DD) {
        int d = t;
        #pragma unroll
        for (int r = 0; r < 8; r++) {
            float s = part_s[0][r][d] + part_s[1][r][d] + part_s[2][r][d] + part_s[3][r][d];
            agg_s[r][d] = s * inv_s[r];
        }
    }
    __syncthreads();

    {   // projections + BN + SELU: thread = (o in 64, rr in 4) -> 2 rows
        int o = t & 63, rr = t >> 6;
        int r0 = rr * 2, r1 = r0 + 1;
        float acc0 = pwa_b[o] + pwo_b[o];
        float acc1 = acc0;
        #pragma unroll 8
        for (int d = 0; d < DD; d++) {
            float wa = pwa_w[d * DD + o];
            float wo = pwo_w[d * DD + o];
            acc0 = fmaf(agg_s[r0][d], wa, acc0);
            acc0 = fmaf(xrow_s[r0][d], wo, acc0);
            acc1 = fmaf(agg_s[r1][d], wa, acc1);
            acc1 = fmaf(xrow_s[r1][d], wo, acc1);
        }
        const float BNF = 0.9999950000374997f;   // 1/sqrt(1+1e-5)
        float gm = bn_gamma[o] * BNF, bt = bn_beta[o];
        acc0 = acc0 * gm + bt;
        acc1 = acc1 * gm + bt;
        const float SC = 1.0507009873554805f, AL = 1.6732632423543772f;
        float v0 = acc0 > 0.f ? SC * acc0 : SC * AL * expm1f(acc0);
        float v1 = acc1 > 0.f ? SC * acc1 : SC * AL * expm1f(acc1);
        g_h[((size_t)b * NN + ibase + r0) * DD + o] = v0;
        g_h[((size_t)b * NN + ibase + r1) * DD + o] = v1;
        h_s[r0][o] = v0; h_s[r1][o] = v1;
    }
    __syncthreads();

    {   // pool scores
        int r = t >> 5, lane = t & 31;
        float z = h_s[r][lane] * pool_w[lane] + h_s[r][lane + 32] * pool_w[lane + 32];
        #pragma unroll
        for (int off = 16; off; off >>= 1) z += __shfl_xor_sync(0xffffffffu, z, off);
        if (lane == 0) {
            z += pool_b[0];
            g_scores[b * NN + ibase + r] = __fdividef(1.0f, 1.0f + __expf(-z));
        }
    }
}

// ---------------------------------------------------------------------------
// K3: per batch: full bitonic sort of 512 (score desc, idx asc) keys,
//     emit top-256 rows of h*score in rank order.
// ---------------------------------------------------------------------------
__global__ __launch_bounds__(512)
void k3_topk(float* __restrict__ out) {
    __shared__ unsigned long long keys[NN];
    __shared__ int   s_idx[KNODES];
    __shared__ float s_sc[KNODES];
    int b = blockIdx.x, t = threadIdx.x;
    float s = g_scores[b * NN + t];
    // scores in (0,1): positive-float bit pattern is order-preserving.
    // (score desc, idx asc) <=> key desc with (0xFFFF - idx) in low bits.
    keys[t] = ((unsigned long long)__float_as_uint(s) << 16) | (unsigned)(0xFFFF - t);
    __syncthreads();
    for (int k = 2; k <= NN; k <<= 1) {
        for (int j = k >> 1; j > 0; j >>= 1) {
            int ixj = t ^ j;
            if (ixj > t) {
                unsigned long long a = keys[t], c = keys[ixj];
                bool sw = ((t & k) == 0) ? (a < c) : (a > c);   // descending
                if (sw) { keys[t] = c; keys[ixj] = a; }
            }
            __syncthreads();
        }
    }
    if (t < KNODES) {
        unsigned long long kk = keys[t];
        s_idx[t] = 0xFFFF - (int)(kk & 0xFFFF);
        s_sc[t] = __uint_as_float((unsigned)(kk >> 16));
    }
    __syncthreads();
    const float* hb = g_h + (size_t)b * NN * DD;
    float* ob = out + (size_t)b * KNODES * DD;
    for (int e = t; e < KNODES * DD; e += 512) {
        int r = e >> 6, o = e & 63;
        ob[e] = hb[s_idx[r] * DD + o] * s_sc[r];
    }
}

extern "C" void kernel_launch(void* const* d_in, const int* in_sizes, int n_in,
                              void* d_out, int out_size) {
    const float* x     = (const float*)d_in[0];
    const float* apw   = (const float*)d_in[1];
    const float* apb   = (const float*)d_in[2];
    const float* attw  = (const float*)d_in[3];
    const float* pwa_w = (const float*)d_in[4];
    const float* pwa_b = (const float*)d_in[5];
    const float* pwo_w = (const float*)d_in[6];
    const float* pwo_b = (const float*)d_in[7];
    const float* bng   = (const float*)d_in[8];
    const float* bnb   = (const float*)d_in[9];
    const float* plw   = (const float*)d_in[10];
    const float* plb   = (const float*)d_in[11];
    float* out = (float*)d_out;

    k1_logits<<<dim3(NPAIRS, BATCH), 256>>>(x, apw, apb, attw);
    k2_softagg<<<dim3(NN / 8, BATCH), 256>>>(x, pwa_w, pwa_b, pwo_w, pwo_b,
                                             bng, bnb, plw, plb);
    k3_topk<<<BATCH, 512>>>(out);
}

// round 3
// speedup vs baseline: 1.3492x; 1.3492x over previous
#include <cuda_runtime.h>
#include <cstdint>

#define BATCH   8
#define NN      512
#define DD      64
#define KNODES  256
#define TILE    32
#define NTILES  16      // NN / TILE
#define NPAIRS  136     // NTILES*(NTILES+1)/2
#define PAD_X   68
#define PAD_W   72

// Scratch (device globals: no allocation allowed)
__device__ float g_logits[BATCH * NN * NN];   // 8 MB
__device__ float g_h[BATCH * NN * DD];        // 1 MB
__device__ float g_scores[BATCH * NN];

// k1 dynamic smem layout (float offsets)
#define OFF_XI  0
#define OFF_XJ  (TILE * PAD_X)
#define OFF_WHI (2 * TILE * PAD_X)
#define OFF_WLO (OFF_WHI + DD * PAD_W)
#define OFF_PB  (OFF_WLO + DD * PAD_W)
#define OFF_AW  (OFF_PB + DD)
#define SMEM_FLOATS (OFF_AW + DD)
#define SMEM_BYTES  (SMEM_FLOATS * 4)

__device__ __forceinline__ float fast_tanh(float v) {
    float a = fabsf(v);
    float e = __expf(-2.0f * a);
    float r = __fdividef(1.0f - e, 1.0f + e);
    return copysignf(r, v);
}

__device__ __forceinline__ unsigned f2tf32(float f) {
    unsigned u;
    asm("cvt.rna.tf32.f32 %0, %1;" : "=r"(u) : "f"(f));
    return u;
}

__device__ __forceinline__ void mma_tf32(float* c,
                                         unsigned a0, unsigned a1, unsigned a2, unsigned a3,
                                         unsigned b0, unsigned b1) {
    asm("mma.sync.aligned.m16n8k8.row.col.f32.tf32.tf32.f32 "
        "{%0,%1,%2,%3}, {%4,%5,%6,%7}, {%8,%9}, {%0,%1,%2,%3};"
        : "+f"(c[0]), "+f"(c[1]), "+f"(c[2]), "+f"(c[3])
        : "r"(a0), "r"(a1), "r"(a2), "r"(a3), "r"(b0), "r"(b1));
}

// ---------------------------------------------------------------------------
// K1 (tensor-core): pairwise logits via 3xTF32 mma.
// C[pair, o] = sum_d (x_i,d * x_j,d) * W[d,o]; logits = sum_o tanh(C+pb)*attw
// One CTA per (batch, upper-triangular 32x32 tile pair); mirror-store.
// ---------------------------------------------------------------------------
__global__ __launch_bounds__(256, 2)
void k1_logits_tc(const float* __restrict__ x, const float* __restrict__ W,
                  const float* __restrict__ pb, const float* __restrict__ attw) {
    extern __shared__ float S[];

    int b = blockIdx.y;
    int pp = blockIdx.x;
    int it = 0;
    while (pp >= NTILES - it) { pp -= NTILES - it; it++; }
    int jt = it + pp;

    int t = threadIdx.x, w = t >> 5, lane = t & 31;
    int g = lane >> 2, cc = lane & 3;

    // W splits: whi = tf32(W), wlo = tf32(W - whi). pad 72 -> B-frag LDS conflict-free.
    for (int idx = t; idx < DD * DD; idx += 256) {
        int d = idx >> 6, o = idx & 63;
        float wv = W[idx];
        unsigned hb = f2tf32(wv);
        float hf = __uint_as_float(hb);
        S[OFF_WHI + d * PAD_W + o] = hf;
        S[OFF_WLO + d * PAD_W + o] = __uint_as_float(f2tf32(wv - hf));
    }
    if (t < DD) { S[OFF_PB + t] = pb[t]; S[OFF_AW + t] = attw[t]; }
    const float* xb = x + (size_t)b * NN * DD;
    for (int idx = t; idx < TILE * 16; idx += 256) {
        int r = idx >> 4, c4 = idx & 15;
        float4 vi = ((const float4*)(xb + (it * TILE + r) * DD))[c4];
        *(float4*)&S[OFF_XI + r * PAD_X + c4 * 4] = vi;
        float4 vj = ((const float4*)(xb + (jt * TILE + r) * DD))[c4];
        *(float4*)&S[OFF_XJ + r * PAD_X + c4 * 4] = vj;
    }
    __syncthreads();

    float* L = g_logits + (size_t)b * NN * NN;

    #pragma unroll 1
    for (int p = 0; p < 4; p++) {
        int iL = 4 * w + p;                 // this warp's i row (local)
        float C[2][8][4];                   // [j-half][n-tile][frag]
        #pragma unroll
        for (int h = 0; h < 2; h++)
            #pragma unroll
            for (int nt = 0; nt < 8; nt++)
                #pragma unroll
                for (int q = 0; q < 4; q++) C[h][nt][q] = 0.f;

        #pragma unroll 1
        for (int ks = 0; ks < 8; ks++) {
            int d0 = ks * 8;
            float xic0 = S[OFF_XI + iL * PAD_X + d0 + cc];
            float xic4 = S[OFF_XI + iL * PAD_X + d0 + cc + 4];
            unsigned ah[2][4], al[2][4];
            #pragma unroll
            for (int h = 0; h < 2; h++) {
                int jb = h * 16;
                float xj0 = S[OFF_XJ + (jb + g    ) * PAD_X + d0 + cc];
                float xj8 = S[OFF_XJ + (jb + g + 8) * PAD_X + d0 + cc];
                float yj0 = S[OFF_XJ + (jb + g    ) * PAD_X + d0 + cc + 4];
                float yj8 = S[OFF_XJ + (jb + g + 8) * PAD_X + d0 + cc + 4];
                float p0 = xic0 * xj0, p1 = xic0 * xj8;
                float p2 = xic4 * yj0, p3 = xic4 * yj8;
                ah[h][0] = f2tf32(p0); al[h][0] = f2tf32(p0 - __uint_as_float(ah[h][0]));
                ah[h][1] = f2tf32(p1); al[h][1] = f2tf32(p1 - __uint_as_float(ah[h][1]));
                ah[h][2] = f2tf32(p2); al[h][2] = f2tf32(p2 - __uint_as_float(ah[h][2]));
                ah[h][3] = f2tf32(p3); al[h][3] = f2tf32(p3 - __uint_as_float(ah[h][3]));
            }
            #pragma unroll
            for (int nt = 0; nt < 8; nt++) {
                int ob = nt * 8 + g;
                unsigned bh0 = __float_as_uint(S[OFF_WHI + (d0 + cc    ) * PAD_W + ob]);
                unsigned bh1 = __float_as_uint(S[OFF_WHI + (d0 + cc + 4) * PAD_W + ob]);
                unsigned bl0 = __float_as_uint(S[OFF_WLO + (d0 + cc    ) * PAD_W + ob]);
                unsigned bl1 = __float_as_uint(S[OFF_WLO + (d0 + cc + 4) * PAD_W + ob]);
                #pragma unroll
                for (int h = 0; h < 2; h++) {
                    mma_tf32(C[h][nt], ah[h][0], ah[h][1], ah[h][2], ah[h][3], bh0, bh1);
                    mma_tf32(C[h][nt], al[h][0], al[h][1], al[h][2], al[h][3], bh0, bh1);
                    mma_tf32(C[h][nt], ah[h][0], ah[h][1], ah[h][2], ah[h][3], bl0, bl1);
                }
            }
        }
        // epilogue: tanh(C + pb) . attw, reduce over o (quad shuffle), store + mirror
        int gi = it * TILE + iL;
        #pragma unroll
        for (int h = 0; h < 2; h++) {
            float slo = 0.f, shi = 0.f;
            #pragma unroll
            for (int nt = 0; nt < 8; nt++) {
                int o0 = nt * 8 + 2 * cc, o1 = o0 + 1;
                float pb0 = S[OFF_PB + o0], pb1 = S[OFF_PB + o1];
                float w0  = S[OFF_AW + o0], w1  = S[OFF_AW + o1];
                slo = fmaf(fast_tanh(C[h][nt][0] + pb0), w0, slo);
                slo = fmaf(fast_tanh(C[h][nt][1] + pb1), w1, slo);
                shi = fmaf(fast_tanh(C[h][nt][2] + pb0), w0, shi);
                shi = fmaf(fast_tanh(C[h][nt][3] + pb1), w1, shi);
            }
            slo += __shfl_xor_sync(0xffffffffu, slo, 1);
            slo += __shfl_xor_sync(0xffffffffu, slo, 2);
            shi += __shfl_xor_sync(0xffffffffu, shi, 1);
            shi += __shfl_xor_sync(0xffffffffu, shi, 2);
            if (cc == 0) {
                int gj0 = jt * TILE + h * 16 + g;
                int gj8 = gj0 + 8;
                L[gi * NN + gj0] = slo;
                L[gi * NN + gj8] = shi;
                if (it != jt) {
                    L[gj0 * NN + gi] = slo;
                    L[gj8 * NN + gi] = shi;
                }
            }
        }
    }
}

// ---------------------------------------------------------------------------
// K2: per (b, 8-row block): softmax over j, agg = att @ X, h = agg@pwa + x@pwo
//     + biases, BN(eval), SELU, score = sigmoid(h @ pool_w + pool_b)
// ---------------------------------------------------------------------------
__global__ __launch_bounds__(256)
void k2_softagg(const float* __restrict__ x,
                const float* __restrict__ pwa_w, const float* __restrict__ pwa_b,
                const float* __restrict__ pwo_w, const float* __restrict__ pwo_b,
                const float* __restrict__ bn_gamma, const float* __restrict__ bn_beta,
                const float* __restrict__ pool_w, const float* __restrict__ pool_b) {
    __shared__ float prob_s[NN][8];        // 16 KB: [j][r]
    __shared__ float part_s[4][8][DD];     // 8 KB
    __shared__ float agg_s[8][DD];
    __shared__ float xrow_s[8][DD];
    __shared__ float h_s[8][DD];
    __shared__ float inv_s[8];

    int b = blockIdx.y;
    int ibase = blockIdx.x * 8;
    int t = threadIdx.x;
    const float* xb = x + (size_t)b * NN * DD;

    for (int idx = t; idx < 8 * DD; idx += 256) {
        int r = idx >> 6, d = idx & 63;
        xrow_s[r][d] = xb[(ibase + r) * DD + d];
    }

    {   // softmax (unnormalized) for 8 rows: warp r handles row ibase+r
        int r = t >> 5, lane = t & 31;
        const float* Lrow = g_logits + ((size_t)b * NN + ibase + r) * NN;
        float lv[16];
        float m = -1e30f;
        #pragma unroll
        for (int q = 0; q < 16; q++) { lv[q] = Lrow[lane + q * 32]; m = fmaxf(m, lv[q]); }
        #pragma unroll
        for (int off = 16; off; off >>= 1) m = fmaxf(m, __shfl_xor_sync(0xffffffffu, m, off));
        float sum = 0.f;
        #pragma unroll
        for (int q = 0; q < 16; q++) {
            float e = __expf(lv[q] - m);
            prob_s[lane + q * 32][r] = e;
            sum += e;
        }
        #pragma unroll
        for (int off = 16; off; off >>= 1) sum += __shfl_xor_sync(0xffffffffu, sum, off);
        if (lane == 0) inv_s[r] = 1.0f / sum;
    }
    __syncthreads();

    {   // agg partials: thread = (d4 in 16, g in 4, rp in 4) -> 4 d x 2 rows
        int d4 = t & 15, g = (t >> 4) & 3, rp = t >> 6;
        int r0 = rp * 2;
        float a0x=0,a0y=0,a0z=0,a0w=0, a1x=0,a1y=0,a1z=0,a1w=0;
        const float4* xb4 = (const float4*)xb;
        for (int jj = 0; jj < 128; jj++) {
            int j = g * 128 + jj;
            float4 xv = xb4[j * 16 + d4];
            float2 pr = *(const float2*)&prob_s[j][r0];
            a0x = fmaf(pr.x, xv.x, a0x); a0y = fmaf(pr.x, xv.y, a0y);
            a0z = fmaf(pr.x, xv.z, a0z); a0w = fmaf(pr.x, xv.w, a0w);
            a1x = fmaf(pr.y, xv.x, a1x); a1y = fmaf(pr.y, xv.y, a1y);
            a1z = fmaf(pr.y, xv.z, a1z); a1w = fmaf(pr.y, xv.w, a1w);
        }
        part_s[g][r0][d4*4+0] = a0x; part_s[g][r0][d4*4+1] = a0y;
        part_s[g][r0][d4*4+2] = a0z; part_s[g][r0][d4*4+3] = a0w;
        part_s[g][r0+1][d4*4+0] = a1x; part_s[g][r0+1][d4*4+1] = a1y;
        part_s[g][r0+1][d4*4+2] = a1z; part_s[g][r0+1][d4*4+3] = a1w;
    }
    __syncthreads();

    if (t < DD) {
        int d = t;
        #pragma unroll
        for (int r = 0; r < 8; r++) {
            float s = part_s[0][r][d] + part_s[1][r][d] + part_s[2][r][d] + part_s[3][r][d];
            agg_s[r][d] = s * inv_s[r];
        }
    }
    __syncthreads();

    {   // projections + BN + SELU: thread = (o in 64, rr in 4) -> 2 rows
        int o = t & 63, rr = t >> 6;
        int r0 = rr * 2, r1 = r0 + 1;
        float acc0 = pwa_b[o] + pwo_b[o];
        float acc1 = acc0;
        #pragma unroll 8
        for (int d = 0; d < DD; d++) {
            float wa = pwa_w[d * DD + o];
            float wo = pwo_w[d * DD + o];
            acc0 = fmaf(agg_s[r0][d], wa, acc0);
            acc0 = fmaf(xrow_s[r0][d], wo, acc0);
            acc1 = fmaf(agg_s[r1][d], wa, acc1);
            acc1 = fmaf(xrow_s[r1][d], wo, acc1);
        }
        const float BNF = 0.9999950000374997f;   // 1/sqrt(1+1e-5)
        float gm = bn_gamma[o] * BNF, bt = bn_beta[o];
        acc0 = acc0 * gm + bt;
        acc1 = acc1 * gm + bt;
        const float SC = 1.0507009873554805f, AL = 1.6732632423543772f;
        float v0 = acc0 > 0.f ? SC * acc0 : SC * AL * expm1f(acc0);
        float v1 = acc1 > 0.f ? SC * acc1 : SC * AL * expm1f(acc1);
        g_h[((size_t)b * NN + ibase + r0) * DD + o] = v0;
        g_h[((size_t)b * NN + ibase + r1) * DD + o] = v1;
        h_s[r0][o] = v0; h_s[r1][o] = v1;
    }
    __syncthreads();

    {   // pool scores
        int r = t >> 5, lane = t & 31;
        float z = h_s[r][lane] * pool_w[lane] + h_s[r][lane + 32] * pool_w[lane + 32];
        #pragma unroll
        for (int off = 16; off; off >>= 1) z += __shfl_xor_sync(0xffffffffu, z, off);
        if (lane == 0) {
            z += pool_b[0];
            g_scores[b * NN + ibase + r] = __fdividef(1.0f, 1.0f + __expf(-z));
        }
    }
}

// ---------------------------------------------------------------------------
// K3: per batch: full bitonic sort of 512 (score desc, idx asc) keys,
//     emit top-256 rows of h*score in rank order.
// ---------------------------------------------------------------------------
__global__ __launch_bounds__(512)
void k3_topk(float* __restrict__ out) {
    __shared__ unsigned long long keys[NN];
    __shared__ int   s_idx[KNODES];
    __shared__ float s_sc[KNODES];
    int b = blockIdx.x, t = threadIdx.x;
    float s = g_scores[b * NN + t];
    // scores in (0,1): positive-float bit pattern is order-preserving.
    keys[t] = ((unsigned long long)__float_as_uint(s) << 16) | (unsigned)(0xFFFF - t);
    __syncthreads();
    for (int k = 2; k <= NN; k <<= 1) {
        for (int j = k >> 1; j > 0; j >>= 1) {
            int ixj = t ^ j;
            if (ixj > t) {
                unsigned long long a = keys[t], c = keys[ixj];
                bool sw = ((t & k) == 0) ? (a < c) : (a > c);   // descending
                if (sw) { keys[t] = c; keys[ixj] = a; }
            }
            __syncthreads();
        }
    }
    if (t < KNODES) {
        unsigned long long kk = keys[t];
        s_idx[t] = 0xFFFF - (int)(kk & 0xFFFF);
        s_sc[t] = __uint_as_float((unsigned)(kk >> 16));
    }
    __syncthreads();
    const float* hb = g_h + (size_t)b * NN * DD;
    float* ob = out + (size_t)b * KNODES * DD;
    for (int e = t; e < KNODES * DD; e += 512) {
        int r = e >> 6, o = e & 63;
        ob[e] = hb[s_idx[r] * DD + o] * s_sc[r];
    }
}

extern "C" void kernel_launch(void* const* d_in, const int* in_sizes, int n_in,
                              void* d_out, int out_size) {
    const float* x     = (const float*)d_in[0];
    const float* apw   = (const float*)d_in[1];
    const float* apb   = (const float*)d_in[2];
    const float* attw  = (const float*)d_in[3];
    const float* pwa_w = (const float*)d_in[4];
    const float* pwa_b = (const float*)d_in[5];
    const float* pwo_w = (const float*)d_in[6];
    const float* pwo_b = (const float*)d_in[7];
    const float* bng   = (const float*)d_in[8];
    const float* bnb   = (const float*)d_in[9];
    const float* plw   = (const float*)d_in[10];
    const float* plb   = (const float*)d_in[11];
    float* out = (float*)d_out;

    cudaFuncSetAttribute(k1_logits_tc, cudaFuncAttributeMaxDynamicSharedMemorySize, SMEM_BYTES);
    k1_logits_tc<<<dim3(NPAIRS, BATCH), 256, SMEM_BYTES>>>(x, apw, apb, attw);
    k2_softagg<<<dim3(NN / 8, BATCH), 256>>>(x, pwa_w, pwa_b, pwo_w, pwo_b,
                                             bng, bnb, plw, plb);
    k3_topk<<<BATCH, 512>>>(out);
}

// round 4
// speedup vs baseline: 1.3881x; 1.0288x over previous
#include <cuda_runtime.h>
#include <cstdint>

#define BATCH   8
#define NN      512
#define DD      64
#define KNODES  256
#define TILE    32
#define NTILES  16      // NN / TILE
#define NPAIRS  136     // NTILES*(NTILES+1)/2
#define PAD_X   68
#define PAD_W   72

// Scratch (device globals: no allocation allowed)
__device__ float g_logits[BATCH * NN * NN];   // 8 MB
__device__ float g_h[BATCH * NN * DD];        // 1 MB
__device__ float g_scores[BATCH * NN];

// k1 dynamic smem layout (float offsets)
#define OFF_XI  0
#define OFF_XJ  (TILE * PAD_X)
#define OFF_WHI (2 * TILE * PAD_X)
#define OFF_WLO (OFF_WHI + DD * PAD_W)
#define OFF_PB  (OFF_WLO + DD * PAD_W)
#define OFF_AW  (OFF_PB + DD)
#define SMEM_FLOATS (OFF_AW + DD)
#define SMEM_BYTES  (SMEM_FLOATS * 4)

__device__ __forceinline__ float fast_tanh(float v) {
    float a = fabsf(v);
    float e = __expf(-2.0f * a);
    float r = __fdividef(1.0f - e, 1.0f + e);
    return copysignf(r, v);
}

__device__ __forceinline__ unsigned f2tf32(float f) {
    unsigned u;
    asm("cvt.rna.tf32.f32 %0, %1;" : "=r"(u) : "f"(f));
    return u;
}

__device__ __forceinline__ void mma_tf32(float* c,
                                         unsigned a0, unsigned a1, unsigned a2, unsigned a3,
                                         unsigned b0, unsigned b1) {
    asm("mma.sync.aligned.m16n8k8.row.col.f32.tf32.tf32.f32 "
        "{%0,%1,%2,%3}, {%4,%5,%6,%7}, {%8,%9}, {%0,%1,%2,%3};"
        : "+f"(c[0]), "+f"(c[1]), "+f"(c[2]), "+f"(c[3])
        : "r"(a0), "r"(a1), "r"(a2), "r"(a3), "r"(b0), "r"(b1));
}

// ---------------------------------------------------------------------------
// K1 (tensor-core): pairwise logits via 3xTF32 mma, split-pass ordering to
// break accumulator RAW chains (16-MMA reuse distance).
// C[pair, o] = sum_d (x_i,d * x_j,d) * W[d,o]; logits = sum_o tanh(C+pb)*attw
// One CTA per (batch, upper-triangular 32x32 tile pair); mirror-store.
// ---------------------------------------------------------------------------
__global__ __launch_bounds__(256, 2)
void k1_logits_tc(const float* __restrict__ x, const float* __restrict__ W,
                  const float* __restrict__ pb, const float* __restrict__ attw) {
    extern __shared__ float S[];

    int b = blockIdx.y;
    int pp = blockIdx.x;
    int it = 0;
    while (pp >= NTILES - it) { pp -= NTILES - it; it++; }
    int jt = it + pp;

    int t = threadIdx.x, w = t >> 5, lane = t & 31;
    int g = lane >> 2, cc = lane & 3;

    // W splits: whi = tf32(W), wlo = tf32(W - whi). pad 72 -> B-frag LDS conflict-free.
    for (int idx = t; idx < DD * DD; idx += 256) {
        int d = idx >> 6, o = idx & 63;
        float wv = W[idx];
        unsigned hb = f2tf32(wv);
        float hf = __uint_as_float(hb);
        S[OFF_WHI + d * PAD_W + o] = hf;
        S[OFF_WLO + d * PAD_W + o] = __uint_as_float(f2tf32(wv - hf));
    }
    if (t < DD) { S[OFF_PB + t] = pb[t]; S[OFF_AW + t] = attw[t]; }
    const float* xb = x + (size_t)b * NN * DD;
    for (int idx = t; idx < TILE * 16; idx += 256) {
        int r = idx >> 4, c4 = idx & 15;
        float4 vi = ((const float4*)(xb + (it * TILE + r) * DD))[c4];
        *(float4*)&S[OFF_XI + r * PAD_X + c4 * 4] = vi;
        float4 vj = ((const float4*)(xb + (jt * TILE + r) * DD))[c4];
        *(float4*)&S[OFF_XJ + r * PAD_X + c4 * 4] = vj;
    }
    __syncthreads();

    float* L = g_logits + (size_t)b * NN * NN;

    #pragma unroll 1
    for (int p = 0; p < 4; p++) {
        int iL = 4 * w + p;                 // this warp's i row (local)
        float C[2][8][4];                   // [j-half][n-tile][frag]
        #pragma unroll
        for (int h = 0; h < 2; h++)
            #pragma unroll
            for (int nt = 0; nt < 8; nt++)
                #pragma unroll
                for (int q = 0; q < 4; q++) C[h][nt][q] = 0.f;

        #pragma unroll 1
        for (int ks = 0; ks < 8; ks++) {
            int d0 = ks * 8;
            float xic0 = S[OFF_XI + iL * PAD_X + d0 + cc];
            float xic4 = S[OFF_XI + iL * PAD_X + d0 + cc + 4];
            unsigned ah[2][4], al[2][4];
            #pragma unroll
            for (int h = 0; h < 2; h++) {
                int jb = h * 16;
                float xj0 = S[OFF_XJ + (jb + g    ) * PAD_X + d0 + cc];
                float xj8 = S[OFF_XJ + (jb + g + 8) * PAD_X + d0 + cc];
                float yj0 = S[OFF_XJ + (jb + g    ) * PAD_X + d0 + cc + 4];
                float yj8 = S[OFF_XJ + (jb + g + 8) * PAD_X + d0 + cc + 4];
                float p0 = xic0 * xj0, p1 = xic0 * xj8;
                float p2 = xic4 * yj0, p3 = xic4 * yj8;
                ah[h][0] = f2tf32(p0); al[h][0] = f2tf32(p0 - __uint_as_float(ah[h][0]));
                ah[h][1] = f2tf32(p1); al[h][1] = f2tf32(p1 - __uint_as_float(ah[h][1]));
                ah[h][2] = f2tf32(p2); al[h][2] = f2tf32(p2 - __uint_as_float(ah[h][2]));
                ah[h][3] = f2tf32(p3); al[h][3] = f2tf32(p3 - __uint_as_float(ah[h][3]));
            }
            // Pass 1: a_hi * b_hi over all 16 accumulators (no RAW chains)
            #pragma unroll
            for (int nt = 0; nt < 8; nt++) {
                int ob = nt * 8 + g;
                unsigned bh0 = __float_as_uint(S[OFF_WHI + (d0 + cc    ) * PAD_W + ob]);
                unsigned bh1 = __float_as_uint(S[OFF_WHI + (d0 + cc + 4) * PAD_W + ob]);
                mma_tf32(C[0][nt], ah[0][0], ah[0][1], ah[0][2], ah[0][3], bh0, bh1);
                mma_tf32(C[1][nt], ah[1][0], ah[1][1], ah[1][2], ah[1][3], bh0, bh1);
            }
            // Pass 2: a_lo * b_hi
            #pragma unroll
            for (int nt = 0; nt < 8; nt++) {
                int ob = nt * 8 + g;
                unsigned bh0 = __float_as_uint(S[OFF_WHI + (d0 + cc    ) * PAD_W + ob]);
                unsigned bh1 = __float_as_uint(S[OFF_WHI + (d0 + cc + 4) * PAD_W + ob]);
                mma_tf32(C[0][nt], al[0][0], al[0][1], al[0][2], al[0][3], bh0, bh1);
                mma_tf32(C[1][nt], al[1][0], al[1][1], al[1][2], al[1][3], bh0, bh1);
            }
            // Pass 3: a_hi * b_lo
            #pragma unroll
            for (int nt = 0; nt < 8; nt++) {
                int ob = nt * 8 + g;
                unsigned bl0 = __float_as_uint(S[OFF_WLO + (d0 + cc    ) * PAD_W + ob]);
                unsigned bl1 = __float_as_uint(S[OFF_WLO + (d0 + cc + 4) * PAD_W + ob]);
                mma_tf32(C[0][nt], ah[0][0], ah[0][1], ah[0][2], ah[0][3], bl0, bl1);
                mma_tf32(C[1][nt], ah[1][0], ah[1][1], ah[1][2], ah[1][3], bl0, bl1);
            }
        }
        // epilogue: tanh(C + pb) . attw, reduce over o (quad shuffle), store + mirror
        int gi = it * TILE + iL;
        #pragma unroll
        for (int h = 0; h < 2; h++) {
            float slo = 0.f, shi = 0.f;
            #pragma unroll
            for (int nt = 0; nt < 8; nt++) {
                int o0 = nt * 8 + 2 * cc, o1 = o0 + 1;
                float pb0 = S[OFF_PB + o0], pb1 = S[OFF_PB + o1];
                float w0  = S[OFF_AW + o0], w1  = S[OFF_AW + o1];
                slo = fmaf(fast_tanh(C[h][nt][0] + pb0), w0, slo);
                slo = fmaf(fast_tanh(C[h][nt][1] + pb1), w1, slo);
                shi = fmaf(fast_tanh(C[h][nt][2] + pb0), w0, shi);
                shi = fmaf(fast_tanh(C[h][nt][3] + pb1), w1, shi);
            }
            slo += __shfl_xor_sync(0xffffffffu, slo, 1);
            slo += __shfl_xor_sync(0xffffffffu, slo, 2);
            shi += __shfl_xor_sync(0xffffffffu, shi, 1);
            shi += __shfl_xor_sync(0xffffffffu, shi, 2);
            if (cc == 0) {
                int gj0 = jt * TILE + h * 16 + g;
                int gj8 = gj0 + 8;
                L[gi * NN + gj0] = slo;
                L[gi * NN + gj8] = shi;
                if (it != jt) {
                    L[gj0 * NN + gi] = slo;
                    L[gj8 * NN + gi] = shi;
                }
            }
        }
    }
}

// ---------------------------------------------------------------------------
// K2: per (b, 8-row block): softmax over j, agg = att @ X, h = agg@pwa + x@pwo
//     + biases, BN(eval), SELU, score = sigmoid(h @ pool_w + pool_b)
// ---------------------------------------------------------------------------
__global__ __launch_bounds__(256)
void k2_softagg(const float* __restrict__ x,
                const float* __restrict__ pwa_w, const float* __restrict__ pwa_b,
                const float* __restrict__ pwo_w, const float* __restrict__ pwo_b,
                const float* __restrict__ bn_gamma, const float* __restrict__ bn_beta,
                const float* __restrict__ pool_w, const float* __restrict__ pool_b) {
    __shared__ float prob_s[NN][8];        // 16 KB: [j][r]
    __shared__ float part_s[4][8][DD];     // 8 KB
    __shared__ float agg_s[8][DD];
    __shared__ float xrow_s[8][DD];
    __shared__ float h_s[8][DD];
    __shared__ float inv_s[8];

    int b = blockIdx.y;
    int ibase = blockIdx.x * 8;
    int t = threadIdx.x;
    const float* xb = x + (size_t)b * NN * DD;

    for (int idx = t; idx < 8 * DD; idx += 256) {
        int r = idx >> 6, d = idx & 63;
        xrow_s[r][d] = xb[(ibase + r) * DD + d];
    }

    {   // softmax (unnormalized) for 8 rows: warp r handles row ibase+r
        int r = t >> 5, lane = t & 31;
        const float* Lrow = g_logits + ((size_t)b * NN + ibase + r) * NN;
        float lv[16];
        float m = -1e30f;
        #pragma unroll
        for (int q = 0; q < 16; q++) { lv[q] = Lrow[lane + q * 32]; m = fmaxf(m, lv[q]); }
        #pragma unroll
        for (int off = 16; off; off >>= 1) m = fmaxf(m, __shfl_xor_sync(0xffffffffu, m, off));
        float sum = 0.f;
        #pragma unroll
        for (int q = 0; q < 16; q++) {
            float e = __expf(lv[q] - m);
            prob_s[lane + q * 32][r] = e;
            sum += e;
        }
        #pragma unroll
        for (int off = 16; off; off >>= 1) sum += __shfl_xor_sync(0xffffffffu, sum, off);
        if (lane == 0) inv_s[r] = 1.0f / sum;
    }
    __syncthreads();

    {   // agg partials: thread = (d4 in 16, g in 4, rp in 4) -> 4 d x 2 rows
        int d4 = t & 15, g = (t >> 4) & 3, rp = t >> 6;
        int r0 = rp * 2;
        float a0x=0,a0y=0,a0z=0,a0w=0, a1x=0,a1y=0,a1z=0,a1w=0;
        const float4* xb4 = (const float4*)xb;
        for (int jj = 0; jj < 128; jj++) {
            int j = g * 128 + jj;
            float4 xv = xb4[j * 16 + d4];
            float2 pr = *(const float2*)&prob_s[j][r0];
            a0x = fmaf(pr.x, xv.x, a0x); a0y = fmaf(pr.x, xv.y, a0y);
            a0z = fmaf(pr.x, xv.z, a0z); a0w = fmaf(pr.x, xv.w, a0w);
            a1x = fmaf(pr.y, xv.x, a1x); a1y = fmaf(pr.y, xv.y, a1y);
            a1z = fmaf(pr.y, xv.z, a1z); a1w = fmaf(pr.y, xv.w, a1w);
        }
        part_s[g][r0][d4*4+0] = a0x; part_s[g][r0][d4*4+1] = a0y;
        part_s[g][r0][d4*4+2] = a0z; part_s[g][r0][d4*4+3] = a0w;
        part_s[g][r0+1][d4*4+0] = a1x; part_s[g][r0+1][d4*4+1] = a1y;
        part_s[g][r0+1][d4*4+2] = a1z; part_s[g][r0+1][d4*4+3] = a1w;
    }
    __syncthreads();

    if (t < DD) {
        int d = t;
        #pragma unroll
        for (int r = 0; r < 8; r++) {
            float s = part_s[0][r][d] + part_s[1][r][d] + part_s[2][r][d] + part_s[3][r][d];
            agg_s[r][d] = s * inv_s[r];
        }
    }
    __syncthreads();

    {   // projections + BN + SELU: thread = (o in 64, rr in 4) -> 2 rows
        int o = t & 63, rr = t >> 6;
        int r0 = rr * 2, r1 = r0 + 1;
        float acc0 = pwa_b[o] + pwo_b[o];
        float acc1 = acc0;
        #pragma unroll 8
        for (int d = 0; d < DD; d++) {
            float wa = pwa_w[d * DD + o];
            float wo = pwo_w[d * DD + o];
            acc0 = fmaf(agg_s[r0][d], wa, acc0);
            acc0 = fmaf(xrow_s[r0][d], wo, acc0);
            acc1 = fmaf(agg_s[r1][d], wa, acc1);
            acc1 = fmaf(xrow_s[r1][d], wo, acc1);
        }
        const float BNF = 0.9999950000374997f;   // 1/sqrt(1+1e-5)
        float gm = bn_gamma[o] * BNF, bt = bn_beta[o];
        acc0 = acc0 * gm + bt;
        acc1 = acc1 * gm + bt;
        const float SC = 1.0507009873554805f, AL = 1.6732632423543772f;
        float v0 = acc0 > 0.f ? SC * acc0 : SC * AL * expm1f(acc0);
        float v1 = acc1 > 0.f ? SC * acc1 : SC * AL * expm1f(acc1);
        g_h[((size_t)b * NN + ibase + r0) * DD + o] = v0;
        g_h[((size_t)b * NN + ibase + r1) * DD + o] = v1;
        h_s[r0][o] = v0; h_s[r1][o] = v1;
    }
    __syncthreads();

    {   // pool scores
        int r = t >> 5, lane = t & 31;
        float z = h_s[r][lane] * pool_w[lane] + h_s[r][lane + 32] * pool_w[lane + 32];
        #pragma unroll
        for (int off = 16; off; off >>= 1) z += __shfl_xor_sync(0xffffffffu, z, off);
        if (lane == 0) {
            z += pool_b[0];
            g_scores[b * NN + ibase + r] = __fdividef(1.0f, 1.0f + __expf(-z));
        }
    }
}

// ---------------------------------------------------------------------------
// K3: per batch: full bitonic sort of 512 (score desc, idx asc) keys,
//     emit top-256 rows of h*score in rank order.
// ---------------------------------------------------------------------------
__global__ __launch_bounds__(512)
void k3_topk(float* __restrict__ out) {
    __shared__ unsigned long long keys[NN];
    __shared__ int   s_idx[KNODES];
    __shared__ float s_sc[KNODES];
    int b = blockIdx.x, t = threadIdx.x;
    float s = g_scores[b * NN + t];
    // scores in (0,1): positive-float bit pattern is order-preserving.
    keys[t] = ((unsigned long long)__float_as_uint(s) << 16) | (unsigned)(0xFFFF - t);
    __syncthreads();
    for (int k = 2; k <= NN; k <<= 1) {
        for (int j = k >> 1; j > 0; j >>= 1) {
            int ixj = t ^ j;
            if (ixj > t) {
                unsigned long long a = keys[t], c = keys[ixj];
                bool sw = ((t & k) == 0) ? (a < c) : (a > c);   // descending
                if (sw) { keys[t] = c; keys[ixj] = a; }
            }
            __syncthreads();
        }
    }
    if (t < KNODES) {
        unsigned long long kk = keys[t];
        s_idx[t] = 0xFFFF - (int)(kk & 0xFFFF);
        s_sc[t] = __uint_as_float((unsigned)(kk >> 16));
    }
    __syncthreads();
    const float* hb = g_h + (size_t)b * NN * DD;
    float* ob = out + (size_t)b * KNODES * DD;
    for (int e = t; e < KNODES * DD; e += 512) {
        int r = e >> 6, o = e & 63;
        ob[e] = hb[s_idx[r] * DD + o] * s_sc[r];
    }
}

extern "C" void kernel_launch(void* const* d_in, const int* in_sizes, int n_in,
                              void* d_out, int out_size) {
    const float* x     = (const float*)d_in[0];
    const float* apw   = (const float*)d_in[1];
    const float* apb   = (const float*)d_in[2];
    const float* attw  = (const float*)d_in[3];
    const float* pwa_w = (const float*)d_in[4];
    const float* pwa_b = (const float*)d_in[5];
    const float* pwo_w = (const float*)d_in[6];
    const float* pwo_b = (const float*)d_in[7];
    const float* bng   = (const float*)d_in[8];
    const float* bnb   = (const float*)d_in[9];
    const float* plw   = (const float*)d_in[10];
    const float* plb   = (const float*)d_in[11];
    float* out = (float*)d_out;

    cudaFuncSetAttribute(k1_logits_tc, cudaFuncAttributeMaxDynamicSharedMemorySize, SMEM_BYTES);
    k1_logits_tc<<<dim3(NPAIRS, BATCH), 256, SMEM_BYTES>>>(x, apw, apb, attw);
    k2_softagg<<<dim3(NN / 8, BATCH), 256>>>(x, pwa_w, pwa_b, pwo_w, pwo_b,
                                             bng, bnb, plw, plb);
    k3_topk<<<BATCH, 512>>>(out);
}